// round 10
// baseline (speedup 1.0000x reference)
#include <cuda_runtime.h>
#include <cuda_fp16.h>
#include <cstdint>

// Problem constants
#define NIMG   128          // images per input
#define NTOT   256          // stacked rows (a then b)
#define CCH    16           // channels
#define HP     16           // pooled H
#define WP     16           // pooled W
#define DDIM   4096         // CCH*HP*WP
#define TILE   32           // pair tile edge
#define NTROW  8            // NTOT/TILE
#define NTILES 36           // upper-tri tiles: 8*9/2
#define DCHUNK 256          // d per block (pair kernel)
#define NDCH   16           // DDIM/DCHUNK
#define DSTEP  32           // smem staging depth
#define NSTEPS (DCHUNK / DSTEP)      // 8
#define NBLK_MAIN  (NTILES * NDCH)   // 576 main blocks
#define NBLK_COUNT (NBLK_MAIN + 1)   // + 1 bias-sampling block

// sqrt(0.5*log2(e)) folded into the pooled means: term = ex2(-(d'*r)^2) * r.
#define SQRT_K      0.8493218003f
#define MEAN_SCALE  (0.25f * SQRT_K)

// Scratch.
// f32 pooled data [d][n] — used ONLY by the bias-sampling reference path.
__device__ float g_Mt[DDIM * NTOT];
__device__ float g_Vt[DDIM * NTOT];
// fp16 packed pooled data: g_P[d*128 + q] = { half2(m[2q],m[2q+1]), half2(v[2q],v[2q+1]) }
__device__ uint2 g_P[DDIM * (NTOT / 2)];
__device__ double g_acc;          // zero-init; reset by last block each run
__device__ unsigned int g_done;   // zero-init; reset by last block each run

__device__ __forceinline__ float rsqrt_approx(float x) {
    float y; asm("rsqrt.approx.ftz.f32 %0, %1;" : "=f"(y) : "f"(x)); return y;
}
__device__ __forceinline__ float ex2f32(float x) {
    float y; asm("ex2.approx.ftz.f32 %0, %1;" : "=f"(y) : "f"(x)); return y;
}
__device__ __forceinline__ __half2 h2ex2(__half2 x) {
    unsigned xi = *reinterpret_cast<unsigned*>(&x), yi;
    asm("ex2.approx.f16x2 %0, %1;" : "=r"(yi) : "r"(xi));
    return *reinterpret_cast<__half2*>(&yi);
}
__device__ __forceinline__ __half2 u2h(unsigned x) {
    return *reinterpret_cast<__half2*>(&x);
}
__device__ __forceinline__ unsigned h2u(__half2 x) {
    return *reinterpret_cast<unsigned*>(&x);
}

// fp16 bundle: 2 terms sharing one rsqrt.f16x2 + one ex2.f16x2.
// mi/vi are broadcast half2 (same value both lanes); mj/vj packed pairs.
__device__ __forceinline__ __half2 bundle_f16(__half2 mi, __half2 vi,
                                              __half2 mj, __half2 vj,
                                              __half2 acc) {
    __half2 d = __hsub2(mi, mj);
    __half2 s = __hadd2(vi, vj);
    __half2 r = h2rsqrt(s);
    __half2 t = __hmul2(d, r);
    __half2 u = __hmul2(t, __hneg2(t));
    return __hfma2(h2ex2(u), r, acc);
}

// f32 reference term (exact-path analog; means already carry SQRT_K).
__device__ __forceinline__ float term_f32(float mi, float vi, float mj, float vj) {
    float s = vi + vj;
    float r = rsqrt_approx(s);
    float t = (mi - mj) * r;
    return ex2f32(-t * t) * r;
}

// ---------------------------------------------------------------------------
// Pooling: one block per (ph, c, half). 256 threads. Processes BOTH mu and
// logvar for its half; writes f32 [d][n] arrays AND the packed fp16 array.
// ---------------------------------------------------------------------------
__global__ __launch_bounds__(256) void pool_kernel(
    const float* __restrict__ mu_a, const float* __restrict__ lv_a,
    const float* __restrict__ mu_b, const float* __restrict__ lv_b)
{
    const int ph  = blockIdx.x;      // 0..15
    const int c   = blockIdx.y;      // 0..15
    const int hf  = blockIdx.z;      // 0: a-rows, 1: b-rows
    const int tid = threadIdx.x;

    const float* muSrc = hf ? mu_b : mu_a;
    const float* lvSrc = hf ? lv_b : lv_a;
    const int n_off = hf * NIMG;

    __shared__ float sM[NIMG * 17];
    __shared__ float sV[NIMG * 17];

    const float2* mu2 = reinterpret_cast<const float2*>(muSrc);
    const float2* lv2 = reinterpret_cast<const float2*>(lvSrc);

    #pragma unroll
    for (int k = 0; k < 8; k++) {
        int o  = tid + 256 * k;      // 0..2047
        int n  = o >> 4;
        int pw = o & 15;
        int i2 = n * 8192 + c * 512 + ph * 32 + pw;
        float2 a0 = mu2[i2];
        float2 a1 = mu2[i2 + 16];
        sM[n * 17 + pw] = (a0.x + a0.y + a1.x + a1.y) * MEAN_SCALE;
        float2 b0 = lv2[i2];
        float2 b1 = lv2[i2 + 16];
        sV[n * 17 + pw] = (__expf(b0.x) + __expf(b0.y) + __expf(b1.x) + __expf(b1.y)) * 0.0625f;
    }
    __syncthreads();

    // f32 writes (sampler reference)
    const int dbase = ((c * 16 + ph) * 16) * NTOT + n_off;
    #pragma unroll
    for (int k = 0; k < 8; k++) {
        int o  = tid + 256 * k;
        int pw = o >> 7;
        int n  = o & 127;
        g_Mt[dbase + pw * NTOT + n] = sM[n * 17 + pw];
        g_Vt[dbase + pw * NTOT + n] = sV[n * 17 + pw];
    }

    // fp16 packed writes: 16 pw x 64 q
    const int pbase = ((c * 16 + ph) * 16) * (NTOT / 2) + n_off / 2;
    #pragma unroll
    for (int k = 0; k < 4; k++) {
        int o  = tid + 256 * k;      // 0..1023
        int pw = o >> 6;
        int q  = o & 63;
        float m0 = sM[(2 * q) * 17 + pw],     m1 = sM[(2 * q + 1) * 17 + pw];
        float v0 = sV[(2 * q) * 17 + pw],     v1 = sV[(2 * q + 1) * 17 + pw];
        uint2 val;
        val.x = h2u(__floats2half2_rn(m0, m1));
        val.y = h2u(__floats2half2_rn(v0, v1));
        g_P[pbase + pw * (NTOT / 2) + q] = val;
    }
}

// ---------------------------------------------------------------------------
// Pair kernel: 576 main blocks + 1 bias-sampling block.
// Full fp16x2 SIMD pipeline: 2 MUFU ops (rsqrt.f16x2, ex2.f16x2) per 2 terms.
// Bias correction: off-diagonal mean bias (coef +16) and diagonal bias
// (coef -128) sampled against the f32 reference arrays.
// ---------------------------------------------------------------------------
__global__ __launch_bounds__(256) void pair_kernel(float* __restrict__ out)
{
    const int tid = threadIdx.x;
    __shared__ float warpsum[8];

    double myContribution = 0.0;

    if (blockIdx.x < NBLK_MAIN) {
        // ---- main pair block ----
        const int tileIdx = blockIdx.x % NTILES;
        const int dch     = blockIdx.x / NTILES;

        int rem = tileIdx;
        int ti = 0;
        while (rem >= NTROW - ti) { rem -= NTROW - ti; ti++; }
        const int tj = ti + rem;

        const int i0h = ti * (TILE / 2);   // uint2-index offset of i-tile
        const int j0h = tj * (TILE / 2);
        const int d0  = dch * DCHUNK;

        const int jx = tid & 15;          // j half2-pair within tile
        const int iy = (tid >> 4) & 15;   // i half2-pair within tile

        __shared__ __align__(16) uint2 sI[2][DSTEP * 16];
        __shared__ __align__(16) uint2 sJ[2][DSTEP * 16];

        float facc0 = 0.f, facc1 = 0.f;

        // loaders: thread covers (dd0, q0) and (dd0+16, q0) for both I and J
        const int dd0 = tid >> 4;     // 0..15
        const int q0  = tid & 15;

        uint2 pI0, pI1, pJ0, pJ1;
        {
            int gA = (d0 + dd0) * (NTOT / 2);
            int gB = (d0 + dd0 + 16) * (NTOT / 2);
            pI0 = g_P[gA + i0h + q0];
            pI1 = g_P[gB + i0h + q0];
            pJ0 = g_P[gA + j0h + q0];
            pJ1 = g_P[gB + j0h + q0];
        }
        sI[0][dd0 * 16 + q0]        = pI0;
        sI[0][(dd0 + 16) * 16 + q0] = pI1;
        sJ[0][dd0 * 16 + q0]        = pJ0;
        sJ[0][(dd0 + 16) * 16 + q0] = pJ1;

        #pragma unroll
        for (int s = 0; s < NSTEPS; s++) {
            const int p = s & 1;
            __syncthreads();

            if (s + 1 < NSTEPS) {
                int gA = (d0 + (s + 1) * DSTEP + dd0) * (NTOT / 2);
                int gB = (d0 + (s + 1) * DSTEP + dd0 + 16) * (NTOT / 2);
                pI0 = g_P[gA + i0h + q0];
                pI1 = g_P[gB + i0h + q0];
                pJ0 = g_P[gA + j0h + q0];
                pJ1 = g_P[gB + j0h + q0];
            }

            __half2 hacc0 = __floats2half2_rn(0.f, 0.f);
            __half2 hacc1 = __floats2half2_rn(0.f, 0.f);

            #pragma unroll 4
            for (int dd = 0; dd < DSTEP; dd++) {
                uint2 I = sI[p][dd * 16 + iy];
                uint2 J = sJ[p][dd * 16 + jx];
                __half2 mi = u2h(I.x), vi = u2h(I.y);
                __half2 mj = u2h(J.x), vj = u2h(J.y);

                hacc0 = bundle_f16(__low2half2(mi),  __low2half2(vi),  mj, vj, hacc0);
                hacc1 = bundle_f16(__high2half2(mi), __high2half2(vi), mj, vj, hacc1);
            }

            facc0 += __low2float(hacc0) + __high2float(hacc0);
            facc1 += __low2float(hacc1) + __high2float(hacc1);

            if (s + 1 < NSTEPS) {
                int q = 1 - p;
                sI[q][dd0 * 16 + q0]        = pI0;
                sI[q][(dd0 + 16) * 16 + q0] = pI1;
                sJ[q][dd0 * 16 + q0]        = pJ0;
                sJ[q][(dd0 + 16) * 16 + q0] = pJ1;
            }
        }

        float v = facc0 + facc1;
        #pragma unroll
        for (int o = 16; o; o >>= 1) v += __shfl_xor_sync(0xffffffffu, v, o);
        if ((tid & 31) == 0) warpsum[tid >> 5] = v;
        __syncthreads();
        if (tid == 0) {
            float b = 0.f;
            #pragma unroll
            for (int k = 0; k < 8; k++) b += warpsum[k];
            double sgn = ((ti < 4) == (tj < 4)) ? 1.0 : -1.0;
            double w   = (ti == tj) ? sgn : 2.0 * sgn;
            myContribution = (double)b * w;
        }
    } else {
        // ---- bias sampling block ----
        // Off-diagonal: 256 threads x 128 dims, bundle (i vs pair (2q,2q+1)).
        const int q   = tid & 127;
        const int i   = (tid * 37 + 5) & 255;
        const int ih  = i >> 1;
        const int ilo = i & 1;

        float S16 = 0.f, S32 = 0.f;

        #pragma unroll 1
        for (int db = 0; db < 128; db += 32) {
            __half2 hacc = __floats2half2_rn(0.f, 0.f);
            float s32 = 0.f;
            #pragma unroll 4
            for (int dd = 0; dd < 32; dd++) {
                int d = db + dd;
                uint2 J = g_P[d * (NTOT / 2) + q];
                uint2 I = g_P[d * (NTOT / 2) + ih];
                __half2 mj = u2h(J.x), vj = u2h(J.y);
                __half2 mi2 = u2h(I.x), vi2 = u2h(I.y);
                __half2 mib = ilo ? __high2half2(mi2) : __low2half2(mi2);
                __half2 vib = ilo ? __high2half2(vi2) : __low2half2(vi2);
                hacc = bundle_f16(mib, vib, mj, vj, hacc);

                float m_i = g_Mt[d * NTOT + i],      v_i = g_Vt[d * NTOT + i];
                float mj0 = g_Mt[d * NTOT + 2 * q],  vj0 = g_Vt[d * NTOT + 2 * q];
                float mj1 = g_Mt[d * NTOT + 2 * q + 1], vj1 = g_Vt[d * NTOT + 2 * q + 1];
                s32 += term_f32(m_i, v_i, mj0, vj0);
                s32 += term_f32(m_i, v_i, mj1, vj1);
            }
            S16 += __low2float(hacc) + __high2float(hacc);
            S32 += s32;
        }
        float diff_od = S16 - S32;   // 256 term-samples per thread (65536 total)

        // Diagonal: thread i = tid, 32 dims.
        float S16d = 0.f, S32d = 0.f;
        {
            const int i2h = tid >> 1;
            const int il  = tid & 1;
            #pragma unroll 4
            for (int d = 0; d < 32; d++) {
                uint2 I = g_P[d * (NTOT / 2) + i2h];
                __half2 m2 = u2h(I.x), v2 = u2h(I.y);
                __half2 mb = il ? __high2half2(m2) : __low2half2(m2);
                __half2 vb = il ? __high2half2(v2) : __low2half2(v2);
                // diag bundle: j == i (both lanes identical); take low lane only
                __half2 dd2 = __hsub2(mb, mb);
                __half2 ss  = __hadd2(vb, vb);
                __half2 r   = h2rsqrt(ss);
                __half2 t   = __hmul2(dd2, r);
                __half2 u   = __hmul2(t, __hneg2(t));
                __half2 pr  = __hmul2(h2ex2(u), r);
                S16d += __low2float(pr);

                float m_i = g_Mt[d * NTOT + tid], v_i = g_Vt[d * NTOT + tid];
                S32d += term_f32(m_i, v_i, m_i, v_i);
            }
        }
        float diff_d = S16d - S32d;  // 32 samples per thread (8192 total)

        // correction per thread; coefficients: +16 off-diag, -128 diag
        float v = 16.0f * diff_od - 128.0f * diff_d;
        #pragma unroll
        for (int o = 16; o; o >>= 1) v += __shfl_xor_sync(0xffffffffu, v, o);
        if ((tid & 31) == 0) warpsum[tid >> 5] = v;
        __syncthreads();
        if (tid == 0) {
            float csum = 0.f;
            #pragma unroll
            for (int k = 0; k < 8; k++) csum += warpsum[k];
            myContribution = (double)csum;
        }
    }

    if (tid == 0) {
        atomicAdd(&g_acc, myContribution);
        __threadfence();
        unsigned n = atomicAdd(&g_done, 1u);
        if (n == NBLK_COUNT - 1) {
            __threadfence();
            double total = *((volatile double*)&g_acc);
            out[0] = (float)total;
            // reset for the next (graph-replayed) run
            *((volatile double*)&g_acc) = 0.0;
            *((volatile unsigned*)&g_done) = 0u;
            __threadfence();
        }
    }
}

extern "C" void kernel_launch(void* const* d_in, const int* in_sizes, int n_in,
                              void* d_out, int out_size)
{
    const float* mu_a = (const float*)d_in[0];
    const float* lv_a = (const float*)d_in[1];
    const float* mu_b = (const float*)d_in[2];
    const float* lv_b = (const float*)d_in[3];
    float* out = (float*)d_out;

    pool_kernel<<<dim3(HP, CCH, 2), 256>>>(mu_a, lv_a, mu_b, lv_b);
    pair_kernel<<<NBLK_COUNT, 256>>>(out);
}

// round 11
// speedup vs baseline: 1.5742x; 1.5742x over previous
#include <cuda_runtime.h>
#include <cuda_fp16.h>
#include <cstdint>

// Problem constants
#define NIMG   128          // images per input
#define NTOT   256          // stacked rows (a then b)
#define CCH    16           // channels
#define HP     16           // pooled H
#define WP     16           // pooled W
#define DDIM   4096         // CCH*HP*WP
#define TILE   32           // pair tile edge
#define NTROW  8            // NTOT/TILE
#define NTILES 36           // upper-tri tiles: 8*9/2
#define DCHUNK 256          // d per block (pair kernel)
#define NDCH   16           // DDIM/DCHUNK
#define DSTEP  64           // smem staging depth
#define NSTEPS (DCHUNK / DSTEP)      // 4
#define NBLK_MAIN  (NTILES * NDCH)   // 576 main blocks
#define NBLK_COUNT (NBLK_MAIN + 1)   // + 1 bias-sampling block

// dynamic smem: 4 arrays x 2 buffers x DSTEP*TILE floats = 64 KB
#define SM_ARR   (DSTEP * TILE)            // 2048 floats per buffer per array
#define SMEM_BYTES (4 * 2 * SM_ARR * 4)    // 65536

// sqrt(0.5*log2(e)) folded into the pooled means: term = ex2(-(d'*r)^2) * r.
#define SQRT_K      0.8493218003f
#define MEAN_SCALE  (0.25f * SQRT_K)

// Scratch: pooled mean/variance, TRANSPOSED layout [d][n] (n contiguous).
__device__ float g_Mt[DDIM * NTOT];
__device__ float g_Vt[DDIM * NTOT];
__device__ double g_acc;          // zero-init; reset by last block each run
__device__ unsigned int g_done;   // zero-init; reset by last block each run

__device__ __forceinline__ float rsqrt_approx(float x) {
    float y; asm("rsqrt.approx.ftz.f32 %0, %1;" : "=f"(y) : "f"(x)); return y;
}
__device__ __forceinline__ float ex2f32(float x) {
    float y; asm("ex2.approx.ftz.f32 %0, %1;" : "=f"(y) : "f"(x)); return y;
}
__device__ __forceinline__ __half2 h2ex2(__half2 x) {
    unsigned xi = *reinterpret_cast<unsigned*>(&x), yi;
    asm("ex2.approx.f16x2 %0, %1;" : "=r"(yi) : "r"(xi));
    return *reinterpret_cast<__half2*>(&yi);
}

// ---------------------------------------------------------------------------
// Pooling: one block per (ph, c, array). 256 threads.
// ---------------------------------------------------------------------------
__global__ __launch_bounds__(256) void pool_kernel(
    const float* __restrict__ mu_a, const float* __restrict__ lv_a,
    const float* __restrict__ mu_b, const float* __restrict__ lv_b)
{
    const int ph  = blockIdx.x;      // 0..15
    const int c   = blockIdx.y;      // 0..15
    const int arr = blockIdx.z;      // 0..3
    const int tid = threadIdx.x;

    const float* src = (arr == 0) ? mu_a : (arr == 1) ? lv_a : (arr == 2) ? mu_b : lv_b;
    float* dst       = (arr & 1) ? g_Vt : g_Mt;
    const int n_off  = (arr < 2) ? 0 : NIMG;
    const bool isVar = (arr & 1);

    __shared__ float s[NIMG * 17];   // padded transpose buffer (n*17 + pw)

    const float2* src2 = reinterpret_cast<const float2*>(src);

    #pragma unroll
    for (int k = 0; k < 8; k++) {
        int o  = tid + 256 * k;      // 0..2047
        int n  = o >> 4;
        int pw = o & 15;
        int i2 = n * 8192 + c * 512 + ph * 32 + pw;
        float2 r0 = src2[i2];
        float2 r1 = src2[i2 + 16];
        float p;
        if (isVar) {
            p = (__expf(r0.x) + __expf(r0.y) + __expf(r1.x) + __expf(r1.y)) * 0.0625f;
        } else {
            p = (r0.x + r0.y + r1.x + r1.y) * MEAN_SCALE;
        }
        s[n * 17 + pw] = p;
    }
    __syncthreads();

    const int dbase = ((c * 16 + ph) * 16) * NTOT + n_off;
    #pragma unroll
    for (int k = 0; k < 8; k++) {
        int o  = tid + 256 * k;
        int pw = o >> 7;
        int n  = o & 127;
        dst[dbase + pw * NTOT + n] = s[n * 17 + pw];
    }
}

// ---------------------------------------------------------------------------
// Pair kernel: 576 main blocks (36 upper-tri tiles x 16 d-chunks) + 1 bias
// sampling block. Double-buffered dynamic smem (DSTEP=64, 4 syncs/block),
// register prefetch, fp16x2 ex2 shared across 2 terms, HFMA2 accumulate
// flushed to f32 every 32 dims.
//
// Systematic fp16 bias cancels to -256*bbar_offdiag (since sum s_i s_j = 0);
// the sampler block estimates it against the f32 reference and corrects.
// ---------------------------------------------------------------------------
__global__ __launch_bounds__(256) void pair_kernel(float* __restrict__ out)
{
    const int tid = threadIdx.x;
    __shared__ float warpsum[8];

    double myContribution = 0.0;

    if (blockIdx.x < NBLK_MAIN) {
        // ---- main pair block ----
        const int tileIdx = blockIdx.x % NTILES;
        const int dch     = blockIdx.x / NTILES;

        int rem = tileIdx;
        int ti = 0;
        while (rem >= NTROW - ti) { rem -= NTROW - ti; ti++; }
        const int tj = ti + rem;

        const int i0 = ti * TILE;
        const int j0 = tj * TILE;
        const int d0 = dch * DCHUNK;

        const int jx = tid & 15;        // j micro-col (pairs of 2)
        const int iy = tid >> 4;        // i micro-row (pairs of 2)

        extern __shared__ float dyn[];
        float* sMi = dyn;                    // [2][SM_ARR]
        float* sVi = dyn + 2 * SM_ARR;
        float* sMj = dyn + 4 * SM_ARR;
        float* sVj = dyn + 6 * SM_ARR;

        float facc0 = 0.f, facc1 = 0.f;

        // loaders: thread covers rows lrow and lrow+32 of each array, float4 lane
        const int lrow  = tid >> 3;          // 0..31
        const int lane4 = (tid & 7) * 4;     // 0,4,..,28

        float4 pf[8];
        {
            int gA = (d0 + lrow) * NTOT;
            int gB = (d0 + lrow + 32) * NTOT;
            pf[0] = *reinterpret_cast<const float4*>(&g_Mt[gA + i0 + lane4]);
            pf[1] = *reinterpret_cast<const float4*>(&g_Vt[gA + i0 + lane4]);
            pf[2] = *reinterpret_cast<const float4*>(&g_Mt[gA + j0 + lane4]);
            pf[3] = *reinterpret_cast<const float4*>(&g_Vt[gA + j0 + lane4]);
            pf[4] = *reinterpret_cast<const float4*>(&g_Mt[gB + i0 + lane4]);
            pf[5] = *reinterpret_cast<const float4*>(&g_Vt[gB + i0 + lane4]);
            pf[6] = *reinterpret_cast<const float4*>(&g_Mt[gB + j0 + lane4]);
            pf[7] = *reinterpret_cast<const float4*>(&g_Vt[gB + j0 + lane4]);
        }
        {
            int oA = lrow * TILE + lane4;
            int oB = (lrow + 32) * TILE + lane4;
            *reinterpret_cast<float4*>(&sMi[oA]) = pf[0];
            *reinterpret_cast<float4*>(&sVi[oA]) = pf[1];
            *reinterpret_cast<float4*>(&sMj[oA]) = pf[2];
            *reinterpret_cast<float4*>(&sVj[oA]) = pf[3];
            *reinterpret_cast<float4*>(&sMi[oB]) = pf[4];
            *reinterpret_cast<float4*>(&sVi[oB]) = pf[5];
            *reinterpret_cast<float4*>(&sMj[oB]) = pf[6];
            *reinterpret_cast<float4*>(&sVj[oB]) = pf[7];
        }

        #pragma unroll
        for (int s = 0; s < NSTEPS; s++) {
            const int pb = (s & 1) * SM_ARR;
            __syncthreads();

            if (s + 1 < NSTEPS) {
                int gA = (d0 + (s + 1) * DSTEP + lrow) * NTOT;
                int gB = (d0 + (s + 1) * DSTEP + lrow + 32) * NTOT;
                pf[0] = *reinterpret_cast<const float4*>(&g_Mt[gA + i0 + lane4]);
                pf[1] = *reinterpret_cast<const float4*>(&g_Vt[gA + i0 + lane4]);
                pf[2] = *reinterpret_cast<const float4*>(&g_Mt[gA + j0 + lane4]);
                pf[3] = *reinterpret_cast<const float4*>(&g_Vt[gA + j0 + lane4]);
                pf[4] = *reinterpret_cast<const float4*>(&g_Mt[gB + i0 + lane4]);
                pf[5] = *reinterpret_cast<const float4*>(&g_Vt[gB + i0 + lane4]);
                pf[6] = *reinterpret_cast<const float4*>(&g_Mt[gB + j0 + lane4]);
                pf[7] = *reinterpret_cast<const float4*>(&g_Vt[gB + j0 + lane4]);
            }

            // two 32-deep fp16-accum halves (same depth as the sampler path)
            #pragma unroll
            for (int h = 0; h < 2; h++) {
                __half2 hacc0 = __floats2half2_rn(0.f, 0.f);
                __half2 hacc1 = __floats2half2_rn(0.f, 0.f);

                #pragma unroll 8
                for (int dd = h * 32; dd < h * 32 + 32; dd++) {
                    float2 mi = *reinterpret_cast<float2*>(&sMi[pb + dd * TILE + 2 * iy]);
                    float2 vi = *reinterpret_cast<float2*>(&sVi[pb + dd * TILE + 2 * iy]);
                    float2 mj = *reinterpret_cast<float2*>(&sMj[pb + dd * TILE + 2 * jx]);
                    float2 vj = *reinterpret_cast<float2*>(&sVj[pb + dd * TILE + 2 * jx]);

                    // row 0 (mi.x, vi.x) vs j-pair
                    {
                        float s0 = vi.x + vj.x, s1 = vi.x + vj.y;
                        float r0 = rsqrt_approx(s0), r1 = rsqrt_approx(s1);
                        float t0 = (mi.x - mj.x) * r0;
                        float t1 = (mi.x - mj.y) * r1;
                        __half2 e = h2ex2(__floats2half2_rn(-t0 * t0, -t1 * t1));
                        hacc0 = __hfma2(e, __floats2half2_rn(r0, r1), hacc0);
                    }
                    // row 1 (mi.y, vi.y) vs j-pair
                    {
                        float s0 = vi.y + vj.x, s1 = vi.y + vj.y;
                        float r0 = rsqrt_approx(s0), r1 = rsqrt_approx(s1);
                        float t0 = (mi.y - mj.x) * r0;
                        float t1 = (mi.y - mj.y) * r1;
                        __half2 e = h2ex2(__floats2half2_rn(-t0 * t0, -t1 * t1));
                        hacc1 = __hfma2(e, __floats2half2_rn(r0, r1), hacc1);
                    }
                }

                facc0 += __low2float(hacc0) + __high2float(hacc0);
                facc1 += __low2float(hacc1) + __high2float(hacc1);
            }

            if (s + 1 < NSTEPS) {
                int qb = ((s + 1) & 1) * SM_ARR;
                int oA = qb + lrow * TILE + lane4;
                int oB = qb + (lrow + 32) * TILE + lane4;
                *reinterpret_cast<float4*>(&sMi[oA]) = pf[0];
                *reinterpret_cast<float4*>(&sVi[oA]) = pf[1];
                *reinterpret_cast<float4*>(&sMj[oA]) = pf[2];
                *reinterpret_cast<float4*>(&sVj[oA]) = pf[3];
                *reinterpret_cast<float4*>(&sMi[oB]) = pf[4];
                *reinterpret_cast<float4*>(&sVi[oB]) = pf[5];
                *reinterpret_cast<float4*>(&sMj[oB]) = pf[6];
                *reinterpret_cast<float4*>(&sVj[oB]) = pf[7];
            }
        }

        float v = facc0 + facc1;
        #pragma unroll
        for (int o = 16; o; o >>= 1) v += __shfl_xor_sync(0xffffffffu, v, o);
        if ((tid & 31) == 0) warpsum[tid >> 5] = v;
        __syncthreads();
        if (tid == 0) {
            float b = 0.f;
            #pragma unroll
            for (int k = 0; k < 8; k++) b += warpsum[k];
            double sgn = ((ti < 4) == (tj < 4)) ? 1.0 : -1.0;
            double w   = (ti == tj) ? sgn : 2.0 * sgn;
            myContribution = (double)b * w;
        }
    } else {
        // ---- bias sampling block ----
        // 256 sample pairs (i, 2q/2q+1) x 128 dims; fp16 path identical to main.
        const int q  = tid & 127;
        const int i  = (tid * 37 + 5) & 255;
        float S16 = 0.f, S32 = 0.f;

        #pragma unroll 1
        for (int db = 0; db < 128; db += 32) {
            __half2 hacc = __floats2half2_rn(0.f, 0.f);
            float s32 = 0.f;
            #pragma unroll 4
            for (int dd = 0; dd < 32; dd++) {
                int d = db + dd;
                float m_i = g_Mt[d * NTOT + i],         v_i = g_Vt[d * NTOT + i];
                float mj0 = g_Mt[d * NTOT + 2 * q],     vj0 = g_Vt[d * NTOT + 2 * q];
                float mj1 = g_Mt[d * NTOT + 2 * q + 1], vj1 = g_Vt[d * NTOT + 2 * q + 1];

                float s0 = v_i + vj0, s1 = v_i + vj1;
                float r0 = rsqrt_approx(s0), r1 = rsqrt_approx(s1);
                float t0 = (m_i - mj0) * r0;
                float t1 = (m_i - mj1) * r1;
                float u0 = -t0 * t0, u1 = -t1 * t1;
                // f32 reference path
                s32 = fmaf(ex2f32(u0), r0, s32);
                s32 = fmaf(ex2f32(u1), r1, s32);
                // f16 path (identical ops to the main loop)
                __half2 e = h2ex2(__floats2half2_rn(u0, u1));
                hacc = __hfma2(e, __floats2half2_rn(r0, r1), hacc);
            }
            S16 += __low2float(hacc) + __high2float(hacc);
            S32 += s32;
        }

        float diff = S16 - S32;
        #pragma unroll
        for (int o = 16; o; o >>= 1) diff += __shfl_xor_sync(0xffffffffu, diff, o);
        if ((tid & 31) == 0) warpsum[tid >> 5] = diff;
        __syncthreads();
        if (tid == 0) {
            float dsum = 0.f;
            #pragma unroll
            for (int k = 0; k < 8; k++) dsum += warpsum[k];
            // correction = +256 * bbar = (4096 / (256*128)) * 256 * sum(diff)/... = 32*sum
            myContribution = 32.0 * (double)dsum;
        }
    }

    if (tid == 0) {
        atomicAdd(&g_acc, myContribution);
        __threadfence();
        unsigned n = atomicAdd(&g_done, 1u);
        if (n == NBLK_COUNT - 1) {
            __threadfence();
            double total = *((volatile double*)&g_acc);
            out[0] = (float)total;
            // reset for the next (graph-replayed) run
            *((volatile double*)&g_acc) = 0.0;
            *((volatile unsigned*)&g_done) = 0u;
            __threadfence();
        }
    }
}

extern "C" void kernel_launch(void* const* d_in, const int* in_sizes, int n_in,
                              void* d_out, int out_size)
{
    const float* mu_a = (const float*)d_in[0];
    const float* lv_a = (const float*)d_in[1];
    const float* mu_b = (const float*)d_in[2];
    const float* lv_b = (const float*)d_in[3];
    float* out = (float*)d_out;

    cudaFuncSetAttribute(pair_kernel,
                         cudaFuncAttributeMaxDynamicSharedMemorySize, SMEM_BYTES);

    pool_kernel<<<dim3(HP, CCH, 4), 256>>>(mu_a, lv_a, mu_b, lv_b);
    pair_kernel<<<NBLK_COUNT, 256, SMEM_BYTES>>>(out);
}

// round 12
// speedup vs baseline: 1.7077x; 1.0848x over previous
#include <cuda_runtime.h>
#include <cuda_fp16.h>
#include <cstdint>

// Problem constants
#define NIMG   128          // images per input
#define NTOT   256          // stacked rows (a then b)
#define CCH    16           // channels
#define HP     16           // pooled H
#define WP     16           // pooled W
#define DDIM   4096         // CCH*HP*WP
#define TILE   32           // pair tile edge
#define NTROW  8            // NTOT/TILE
#define NTILES 36           // upper-tri tiles: 8*9/2
#define DCHUNK 256          // d per block (pair kernel)
#define NDCH   16           // DDIM/DCHUNK
#define DSTEP  32           // smem staging depth
#define NSTEPS (DCHUNK / DSTEP)      // 8
#define NBLK_MAIN  (NTILES * NDCH)   // 576 main blocks
#define NBLK_COUNT (NBLK_MAIN + 1)   // + 1 bias-sampling block

// sqrt(0.5*log2(e)) folded into the pooled means: term = ex2(-(d'*r)^2) * r.
#define SQRT_K      0.8493218003f
#define MEAN_SCALE  (0.25f * SQRT_K)

// Scratch.
// f32 pooled data [d][n] — bias-sampler reference AND identical-value source
// for the packed array below.
__device__ float g_Mt[DDIM * NTOT];
__device__ float g_Vt[DDIM * NTOT];
// Interleaved packed pooled data: g_MV[d*128 + q] = {m[2q], m[2q+1], v[2q], v[2q+1]}
__device__ float4 g_MV[DDIM * (NTOT / 2)];
__device__ double g_acc;          // zero-init; reset by last block each run
__device__ unsigned int g_done;   // zero-init; reset by last block each run

__device__ __forceinline__ float rsqrt_approx(float x) {
    float y; asm("rsqrt.approx.ftz.f32 %0, %1;" : "=f"(y) : "f"(x)); return y;
}
__device__ __forceinline__ float ex2f32(float x) {
    float y; asm("ex2.approx.ftz.f32 %0, %1;" : "=f"(y) : "f"(x)); return y;
}
__device__ __forceinline__ __half2 h2ex2(__half2 x) {
    unsigned xi = *reinterpret_cast<unsigned*>(&x), yi;
    asm("ex2.approx.f16x2 %0, %1;" : "=r"(yi) : "r"(xi));
    return *reinterpret_cast<__half2*>(&yi);
}

// ---------------------------------------------------------------------------
// Pooling: one block per (ph, c, half). 256 threads. Processes BOTH mu and
// logvar for its half; writes the f32 [d][n] arrays and the packed float4.
// ---------------------------------------------------------------------------
__global__ __launch_bounds__(256) void pool_kernel(
    const float* __restrict__ mu_a, const float* __restrict__ lv_a,
    const float* __restrict__ mu_b, const float* __restrict__ lv_b)
{
    const int ph  = blockIdx.x;      // 0..15
    const int c   = blockIdx.y;      // 0..15
    const int hf  = blockIdx.z;      // 0: a-rows, 1: b-rows
    const int tid = threadIdx.x;

    const float* muSrc = hf ? mu_b : mu_a;
    const float* lvSrc = hf ? lv_b : lv_a;
    const int n_off = hf * NIMG;

    __shared__ float sM[NIMG * 17];
    __shared__ float sV[NIMG * 17];

    const float2* mu2 = reinterpret_cast<const float2*>(muSrc);
    const float2* lv2 = reinterpret_cast<const float2*>(lvSrc);

    #pragma unroll
    for (int k = 0; k < 8; k++) {
        int o  = tid + 256 * k;      // 0..2047
        int n  = o >> 4;
        int pw = o & 15;
        int i2 = n * 8192 + c * 512 + ph * 32 + pw;
        float2 a0 = mu2[i2];
        float2 a1 = mu2[i2 + 16];
        sM[n * 17 + pw] = (a0.x + a0.y + a1.x + a1.y) * MEAN_SCALE;
        float2 b0 = lv2[i2];
        float2 b1 = lv2[i2 + 16];
        sV[n * 17 + pw] = (__expf(b0.x) + __expf(b0.y) + __expf(b1.x) + __expf(b1.y)) * 0.0625f;
    }
    __syncthreads();

    // f32 writes (sampler reference)
    const int dbase = ((c * 16 + ph) * 16) * NTOT + n_off;
    #pragma unroll
    for (int k = 0; k < 8; k++) {
        int o  = tid + 256 * k;
        int pw = o >> 7;
        int n  = o & 127;
        g_Mt[dbase + pw * NTOT + n] = sM[n * 17 + pw];
        g_Vt[dbase + pw * NTOT + n] = sV[n * 17 + pw];
    }

    // packed float4 writes: 16 pw x 64 q
    const int pbase = ((c * 16 + ph) * 16) * (NTOT / 2) + n_off / 2;
    #pragma unroll
    for (int k = 0; k < 4; k++) {
        int o  = tid + 256 * k;      // 0..1023
        int pw = o >> 6;
        int q  = o & 63;
        float4 val;
        val.x = sM[(2 * q) * 17 + pw];
        val.y = sM[(2 * q + 1) * 17 + pw];
        val.z = sV[(2 * q) * 17 + pw];
        val.w = sV[(2 * q + 1) * 17 + pw];
        g_MV[pbase + pw * (NTOT / 2) + q] = val;
    }
}

// ---------------------------------------------------------------------------
// Pair kernel: 576 main blocks (36 upper-tri tiles x 16 d-chunks) + 1 bias
// sampling block. Double-buffered smem of packed float4 {m0,m1,v0,v1};
// one LDS.128 per side per bundle. fp16x2 ex2 shared across 2 terms, HFMA2
// accumulate flushed to f32 every 32 dims.
//
// Systematic fp16 bias cancels to -256*bbar_offdiag (since sum s_i s_j = 0);
// the sampler block estimates bbar against the f32 reference and corrects.
// ---------------------------------------------------------------------------
__global__ __launch_bounds__(256) void pair_kernel(float* __restrict__ out)
{
    const int tid = threadIdx.x;
    __shared__ float warpsum[8];

    double myContribution = 0.0;

    if (blockIdx.x < NBLK_MAIN) {
        // ---- main pair block ----
        const int tileIdx = blockIdx.x % NTILES;
        const int dch     = blockIdx.x / NTILES;

        int rem = tileIdx;
        int ti = 0;
        while (rem >= NTROW - ti) { rem -= NTROW - ti; ti++; }
        const int tj = ti + rem;

        const int i0h = ti * (TILE / 2);   // float4-index offset of i-tile
        const int j0h = tj * (TILE / 2);
        const int d0  = dch * DCHUNK;

        const int jx = tid & 15;          // j pair index within tile
        const int iy = tid >> 4;          // i pair index within tile

        __shared__ __align__(16) float4 sI[2][DSTEP * 16];
        __shared__ __align__(16) float4 sJ[2][DSTEP * 16];

        float facc0 = 0.f, facc1 = 0.f;

        // loaders: thread covers (dd0, q0) and (dd0+16, q0) for both I and J
        const int dd0 = tid >> 4;     // 0..15
        const int q0  = tid & 15;

        float4 pI0, pI1, pJ0, pJ1;
        {
            int gA = (d0 + dd0) * (NTOT / 2);
            int gB = (d0 + dd0 + 16) * (NTOT / 2);
            pI0 = g_MV[gA + i0h + q0];
            pI1 = g_MV[gB + i0h + q0];
            pJ0 = g_MV[gA + j0h + q0];
            pJ1 = g_MV[gB + j0h + q0];
        }
        sI[0][dd0 * 16 + q0]        = pI0;
        sI[0][(dd0 + 16) * 16 + q0] = pI1;
        sJ[0][dd0 * 16 + q0]        = pJ0;
        sJ[0][(dd0 + 16) * 16 + q0] = pJ1;

        #pragma unroll
        for (int s = 0; s < NSTEPS; s++) {
            const int p = s & 1;
            __syncthreads();

            if (s + 1 < NSTEPS) {
                int gA = (d0 + (s + 1) * DSTEP + dd0) * (NTOT / 2);
                int gB = (d0 + (s + 1) * DSTEP + dd0 + 16) * (NTOT / 2);
                pI0 = g_MV[gA + i0h + q0];
                pI1 = g_MV[gB + i0h + q0];
                pJ0 = g_MV[gA + j0h + q0];
                pJ1 = g_MV[gB + j0h + q0];
            }

            __half2 hacc0 = __floats2half2_rn(0.f, 0.f);
            __half2 hacc1 = __floats2half2_rn(0.f, 0.f);

            #pragma unroll 8
            for (int dd = 0; dd < DSTEP; dd++) {
                float4 I = sI[p][dd * 16 + iy];   // {mi0, mi1, vi0, vi1}
                float4 J = sJ[p][dd * 16 + jx];   // {mj0, mj1, vj0, vj1}

                // row 0 (I.x, I.z) vs j-pair
                {
                    float s0 = I.z + J.z, s1 = I.z + J.w;
                    float r0 = rsqrt_approx(s0), r1 = rsqrt_approx(s1);
                    float t0 = (I.x - J.x) * r0;
                    float t1 = (I.x - J.y) * r1;
                    __half2 e = h2ex2(__floats2half2_rn(-t0 * t0, -t1 * t1));
                    hacc0 = __hfma2(e, __floats2half2_rn(r0, r1), hacc0);
                }
                // row 1 (I.y, I.w) vs j-pair
                {
                    float s0 = I.w + J.z, s1 = I.w + J.w;
                    float r0 = rsqrt_approx(s0), r1 = rsqrt_approx(s1);
                    float t0 = (I.y - J.x) * r0;
                    float t1 = (I.y - J.y) * r1;
                    __half2 e = h2ex2(__floats2half2_rn(-t0 * t0, -t1 * t1));
                    hacc1 = __hfma2(e, __floats2half2_rn(r0, r1), hacc1);
                }
            }

            facc0 += __low2float(hacc0) + __high2float(hacc0);
            facc1 += __low2float(hacc1) + __high2float(hacc1);

            if (s + 1 < NSTEPS) {
                int q = 1 - p;
                sI[q][dd0 * 16 + q0]        = pI0;
                sI[q][(dd0 + 16) * 16 + q0] = pI1;
                sJ[q][dd0 * 16 + q0]        = pJ0;
                sJ[q][(dd0 + 16) * 16 + q0] = pJ1;
            }
        }

        float v = facc0 + facc1;
        #pragma unroll
        for (int o = 16; o; o >>= 1) v += __shfl_xor_sync(0xffffffffu, v, o);
        if ((tid & 31) == 0) warpsum[tid >> 5] = v;
        __syncthreads();
        if (tid == 0) {
            float b = 0.f;
            #pragma unroll
            for (int k = 0; k < 8; k++) b += warpsum[k];
            double sgn = ((ti < 4) == (tj < 4)) ? 1.0 : -1.0;
            double w   = (ti == tj) ? sgn : 2.0 * sgn;
            myContribution = (double)b * w;
        }
    } else {
        // ---- bias sampling block (R9-validated: 128 term-samples/thread,
        //      coefficient 32 = 256 * 4096 / 32768) ----
        const int p0 = tid;
        const int p1 = (tid + 1) & 255;
        float S16 = 0.f, S32 = 0.f;

        #pragma unroll 1
        for (int db = 0; db < 128; db += 32) {
            __half2 hacc = __floats2half2_rn(0.f, 0.f);
            float s32 = 0.f;
            #pragma unroll
            for (int dd = 0; dd < 32; dd += 2) {
                int d = db + dd;
                float m00 = g_Mt[d * NTOT + p0],       m01 = g_Mt[d * NTOT + p1];
                float v00 = g_Vt[d * NTOT + p0],       v01 = g_Vt[d * NTOT + p1];
                float m10 = g_Mt[(d + 1) * NTOT + p0], m11 = g_Mt[(d + 1) * NTOT + p1];
                float v10 = g_Vt[(d + 1) * NTOT + p0], v11 = g_Vt[(d + 1) * NTOT + p1];

                float s0 = v00 + v01, s1 = v10 + v11;
                float r0 = rsqrt_approx(s0), r1 = rsqrt_approx(s1);
                float t0 = (m00 - m01) * r0;
                float t1 = (m10 - m11) * r1;
                float u0 = -t0 * t0, u1 = -t1 * t1;
                // f32 reference path
                s32 = fmaf(ex2f32(u0), r0, s32);
                s32 = fmaf(ex2f32(u1), r1, s32);
                // f16 path (identical op sequence to the main loop)
                __half2 e = h2ex2(__floats2half2_rn(u0, u1));
                hacc = __hfma2(e, __floats2half2_rn(r0, r1), hacc);
            }
            S16 += __low2float(hacc) + __high2float(hacc);
            S32 += s32;
        }

        float diff = S16 - S32;
        #pragma unroll
        for (int o = 16; o; o >>= 1) diff += __shfl_xor_sync(0xffffffffu, diff, o);
        if ((tid & 31) == 0) warpsum[tid >> 5] = diff;
        __syncthreads();
        if (tid == 0) {
            float dsum = 0.f;
            #pragma unroll
            for (int k = 0; k < 8; k++) dsum += warpsum[k];
            myContribution = 32.0 * (double)dsum;
        }
    }

    if (tid == 0) {
        atomicAdd(&g_acc, myContribution);
        __threadfence();
        unsigned n = atomicAdd(&g_done, 1u);
        if (n == NBLK_COUNT - 1) {
            __threadfence();
            double total = *((volatile double*)&g_acc);
            out[0] = (float)total;
            // reset for the next (graph-replayed) run
            *((volatile double*)&g_acc) = 0.0;
            *((volatile unsigned*)&g_done) = 0u;
            __threadfence();
        }
    }
}

extern "C" void kernel_launch(void* const* d_in, const int* in_sizes, int n_in,
                              void* d_out, int out_size)
{
    const float* mu_a = (const float*)d_in[0];
    const float* lv_a = (const float*)d_in[1];
    const float* mu_b = (const float*)d_in[2];
    const float* lv_b = (const float*)d_in[3];
    float* out = (float*)d_out;

    pool_kernel<<<dim3(HP, CCH, 2), 256>>>(mu_a, lv_a, mu_b, lv_b);
    pair_kernel<<<NBLK_COUNT, 256>>>(out);
}